// round 1
// baseline (speedup 1.0000x reference)
#include <cuda_runtime.h>
#include <cuda_fp16.h>
#include <cstdint>

// Problem constants (fixed by the dataset)
#define NL0 8000
#define NL1 4000
#define NL2 2000
#define NTOT 14000
#define FDIM 128
#define NCOL 384

static constexpr float ADJ_SCALE = 4096.0f;
static constexpr float INV_SCALE = 1.0f / 4096.0f;

// ---------------- device scratch (static, no allocations) ----------------
__device__ __half g_adjh[84000000];        // adj0|adj1|adj2 in fp16, scaled
__device__ __half g_hh[NTOT * FDIM];       // h0|h1|h2 fp16
__device__ __half g_wcat[3 * FDIM * NCOL]; // per-j: [128][384] with col block i
__device__ __half g_T[NTOT * NCOL];        // T_j = h_j @ Wcat_j
__device__ __half g_Y[NTOT * NCOL];        // gathered/scattered B operand
__device__ float  g_Z[NTOT * NCOL];        // big GEMM output
__device__ int    g_inv0[NL0];
__device__ int    g_inv1[NL1];

// ---------------- prep kernels ----------------
__global__ void k_prep_h(const float* __restrict__ h0, const float* __restrict__ h1,
                         const float* __restrict__ h2, const float* __restrict__ Ws) {
    int t = blockIdx.x * blockDim.x + threadIdx.x;
    // convert h (14000*128 floats, 4 per thread)
    if (t < 448000) {
        int e = t * 4;
        const float* src;
        if (e < 1024000) src = h0 + e;
        else if (e < 1536000) src = h1 + (e - 1024000);
        else src = h2 + (e - 1536000);
        float4 v = *(const float4*)src;
        *(__half2*)(g_hh + e)     = __floats2half2_rn(v.x, v.y);
        *(__half2*)(g_hh + e + 2) = __floats2half2_rn(v.z, v.w);
    }
    // build Wcat: g_wcat[j*49152 + k*384 + i*128 + c] = Ws[i][j][k][c]
    if (t < 3 * FDIM * NCOL) {
        int j = t / 49152;
        int rem = t % 49152;
        int k = rem / 384;
        int col = rem % 384;
        int i = col >> 7;
        int c = col & 127;
        g_wcat[t] = __float2half(Ws[(((size_t)(i * 3 + j) * 128) + k) * 128 + c]);
    }
    if (t < NL0) g_inv0[t] = -1;
    if (t < NL1) g_inv1[t] = -1;
}

__global__ void k_scatter_inv(const int* __restrict__ idx0, const int* __restrict__ idx1) {
    int t = blockIdx.x * blockDim.x + threadIdx.x;
    if (t < NL1) g_inv0[idx0[t]] = t;
    if (t < NL2) g_inv1[idx1[t]] = t;
}

__global__ void k_convert_adj(const float* __restrict__ a0, const float* __restrict__ a1,
                              const float* __restrict__ a2) {
    int t = blockIdx.x * blockDim.x + threadIdx.x;
    if (t >= 21000000) return;
    long long e = (long long)t * 4;
    const float* src;
    if (e < 64000000LL) src = a0 + e;
    else if (e < 80000000LL) src = a1 + (e - 64000000LL);
    else src = a2 + (e - 80000000LL);
    float4 v = *(const float4*)src;
    *(__half2*)(g_adjh + e)     = __floats2half2_rn(v.x * ADJ_SCALE, v.y * ADJ_SCALE);
    *(__half2*)(g_adjh + e + 2) = __floats2half2_rn(v.z * ADJ_SCALE, v.w * ADJ_SCALE);
}

// Gather T -> Y (one 16B chunk per thread)
__global__ void k_gather_y(const int* __restrict__ idx0, const int* __restrict__ idx1) {
    int tid = blockIdx.x * blockDim.x + threadIdx.x;
    if (tid >= NTOT * 3 * 16) return;
    int seg = tid & 15;
    int rest = tid >> 4;
    int j = rest % 3;
    int rg = rest / 3;
    int i, r;
    if (rg < NL0)            { i = 0; r = rg; }
    else if (rg < NL0 + NL1) { i = 1; r = rg - NL0; }
    else                     { i = 2; r = rg - NL0 - NL1; }
    int s = -1;
    if (i == 0) {
        if (j == 0) s = r;
        else if (j == 1) s = g_inv0[r];
        else { int t0 = g_inv0[r]; s = (t0 >= 0) ? g_inv1[t0] : -1; }
    } else if (i == 1) {
        if (j == 0) s = idx0[r];
        else if (j == 1) s = r;
        else s = g_inv1[r];
    } else {
        if (j == 0) s = idx0[idx1[r]];
        else if (j == 1) s = idx1[r];
        else s = r;
    }
    uint4 v = make_uint4(0u, 0u, 0u, 0u);
    if (s >= 0) {
        int srow = (j == 0 ? 0 : (j == 1 ? NL0 : NL0 + NL1)) + s;
        v = *(const uint4*)(g_T + (size_t)srow * NCOL + i * 128 + seg * 8);
    }
    *(uint4*)(g_Y + (size_t)rg * NCOL + j * 128 + seg * 8) = v;
}

// ---------------- GEMM: C[MxN=384] = A[MxK] * B[KxN=384], fp16 in fp32 acc ----------------
struct GemmSeg { int M, K, tileStart; long long Aoff, Boff, Coff; };
struct GemmCfg { int stage; GemmSeg seg[3]; };

#define BM 64
#define BK 32
#define APITCH 40   // halves per A smem row (pad 8)
#define BPITCH 392  // halves per B smem row (pad 8)
#define STG_HALVES (BM * APITCH + BK * BPITCH)  // 2560 + 12544 = 15104
#define SMEM_BYTES (3 * STG_HALVES * 2)         // 90624

__device__ __forceinline__ void cp16(__half* dst, const void* src, bool full) {
    unsigned d = (unsigned)__cvta_generic_to_shared(dst);
    int n = full ? 16 : 0;
    asm volatile("cp.async.cg.shared.global [%0], [%1], 16, %2;\n" :: "r"(d), "l"(src), "r"(n));
}

__global__ void __launch_bounds__(256, 1) k_gemm(GemmCfg cfg) {
    extern __shared__ __align__(16) char smem_raw[];
    __half* smem = (__half*)smem_raw;

    int tid = threadIdx.x;
    int bx = blockIdx.x;
    int s = 0;
    if (bx >= cfg.seg[1].tileStart) s = 1;
    if (bx >= cfg.seg[2].tileStart) s = 2;
    GemmSeg sg = cfg.seg[s];
    int tile = bx - sg.tileStart;
    int row0 = tile * BM;
    int M = sg.M, K = sg.K;
    const __half* A = (cfg.stage == 1 ? g_hh : g_adjh) + sg.Aoff;
    const __half* B = (cfg.stage == 1 ? g_wcat : g_Y) + sg.Boff;

    int lane = tid & 31, wid = tid >> 5;
    int wm = wid >> 2, wn = wid & 3;    // 2 x 4 warp grid; warp tile 32x96

    // per-thread constant load coordinates
    int am = tid >> 2, aseg = tid & 3;  // A: 256 chunks of 16B (8 halves)
    int br[6], bseg[6];
#pragma unroll
    for (int it = 0; it < 6; ++it) { int c = tid + it * 256; br[it] = c / 48; bseg[it] = c % 48; }

    int KT = (K + BK - 1) / BK;

    // tile loader (A predicated on M and K tail; B predicated on K tail)
    auto load_tile = [&](int kt, int st) {
        __half* as = smem + st * STG_HALVES;
        __half* bs = as + BM * APITCH;
        int k0 = kt * BK;
        {
            int grow = row0 + am;
            int gcol = k0 + aseg * 8;
            bool p = (grow < M) && (gcol < K);
            const __half* src = p ? (A + (size_t)grow * K + gcol) : A;
            cp16(as + am * APITCH + aseg * 8, src, p);
        }
#pragma unroll
        for (int it = 0; it < 6; ++it) {
            int kr = k0 + br[it];
            bool p = (kr < K);
            const __half* src = p ? (B + (size_t)kr * NCOL + bseg[it] * 8) : B;
            cp16(bs + br[it] * BPITCH + bseg[it] * 8, src, p);
        }
    };

    for (int st = 0; st < 2; ++st) {
        if (st < KT) load_tile(st, st);
        asm volatile("cp.async.commit_group;\n");
    }

    float acc[2][12][4] = {};
    int a_row = lane & 15;
    int a_col8 = 8 * (lane >> 4);
    int b_row = lane & 15;

    for (int kt = 0; kt < KT; ++kt) {
        asm volatile("cp.async.wait_group 1;\n");
        __syncthreads();
        int nx = kt + 2;
        if (nx < KT) load_tile(nx, nx % 3);
        asm volatile("cp.async.commit_group;\n");

        __half* as = smem + (kt % 3) * STG_HALVES;
        __half* bs = as + BM * APITCH;
#pragma unroll
        for (int kk = 0; kk < 2; ++kk) {
            uint32_t a[2][4];
#pragma unroll
            for (int mt = 0; mt < 2; ++mt) {
                __half* p = as + (size_t)(wm * 32 + mt * 16 + a_row) * APITCH + kk * 16 + a_col8;
                unsigned sp = (unsigned)__cvta_generic_to_shared(p);
                asm volatile("ldmatrix.sync.aligned.m8n8.x4.shared.b16 {%0,%1,%2,%3}, [%4];\n"
                             : "=r"(a[mt][0]), "=r"(a[mt][1]), "=r"(a[mt][2]), "=r"(a[mt][3])
                             : "r"(sp));
            }
#pragma unroll
            for (int nt = 0; nt < 12; ++nt) {
                uint32_t b0, b1;
                __half* p = bs + (size_t)(kk * 16 + b_row) * BPITCH + wn * 96 + nt * 8;
                unsigned sp = (unsigned)__cvta_generic_to_shared(p);
                asm volatile("ldmatrix.sync.aligned.m8n8.x2.trans.shared.b16 {%0,%1}, [%2];\n"
                             : "=r"(b0), "=r"(b1) : "r"(sp));
#pragma unroll
                for (int mt = 0; mt < 2; ++mt) {
                    asm volatile(
                        "mma.sync.aligned.m16n8k16.row.col.f32.f16.f16.f32 "
                        "{%0,%1,%2,%3}, {%4,%5,%6,%7}, {%8,%9}, {%0,%1,%2,%3};\n"
                        : "+f"(acc[mt][nt][0]), "+f"(acc[mt][nt][1]),
                          "+f"(acc[mt][nt][2]), "+f"(acc[mt][nt][3])
                        : "r"(a[mt][0]), "r"(a[mt][1]), "r"(a[mt][2]), "r"(a[mt][3]),
                          "r"(b0), "r"(b1));
                }
            }
        }
    }

    // epilogue store
    int g = lane >> 2, tg = lane & 3;
    if (cfg.stage == 1) {
        __half* C = g_T + sg.Coff;
#pragma unroll
        for (int mt = 0; mt < 2; ++mt) {
            int r1 = row0 + wm * 32 + mt * 16 + g;
            int r2 = r1 + 8;
#pragma unroll
            for (int nt = 0; nt < 12; ++nt) {
                int col = wn * 96 + nt * 8 + tg * 2;
                if (r1 < M) *(__half2*)(C + (size_t)r1 * NCOL + col) =
                    __floats2half2_rn(acc[mt][nt][0], acc[mt][nt][1]);
                if (r2 < M) *(__half2*)(C + (size_t)r2 * NCOL + col) =
                    __floats2half2_rn(acc[mt][nt][2], acc[mt][nt][3]);
            }
        }
    } else {
        float* C = g_Z + sg.Coff;
#pragma unroll
        for (int mt = 0; mt < 2; ++mt) {
            int r1 = row0 + wm * 32 + mt * 16 + g;
            int r2 = r1 + 8;
#pragma unroll
            for (int nt = 0; nt < 12; ++nt) {
                int col = wn * 96 + nt * 8 + tg * 2;
                if (r1 < M) *(float2*)(C + (size_t)r1 * NCOL + col) =
                    make_float2(acc[mt][nt][0], acc[mt][nt][1]);
                if (r2 < M) *(float2*)(C + (size_t)r2 * NCOL + col) =
                    make_float2(acc[mt][nt][2], acc[mt][nt][3]);
            }
        }
    }
}

// ---------------- final epilogue: out = sum_j relu(Z_block_j * inv_scale + b) ----------------
__global__ void k_epilogue(const float* __restrict__ bs, float* __restrict__ out) {
    int tid = blockIdx.x * blockDim.x + threadIdx.x;
    if (tid >= NTOT * FDIM) return;
    int r = tid >> 7;
    int c = tid & 127;
    int i = (r < NL0) ? 0 : ((r < NL0 + NL1) ? 1 : 2);
    float acc = 0.0f;
#pragma unroll
    for (int j = 0; j < 3; ++j) {
        float z = g_Z[(size_t)r * NCOL + j * 128 + c] * INV_SCALE + bs[(i * 3 + j) * 128 + c];
        acc += fmaxf(z, 0.0f);
    }
    out[tid] = acc;
}

// ---------------- host launch ----------------
extern "C" void kernel_launch(void* const* d_in, const int* in_sizes, int n_in,
                              void* d_out, int out_size) {
    const float* adj0 = (const float*)d_in[0];
    const float* adj1 = (const float*)d_in[1];
    const float* adj2 = (const float*)d_in[2];
    const float* h0   = (const float*)d_in[3];
    const float* h1   = (const float*)d_in[4];
    const float* h2   = (const float*)d_in[5];
    const int*   idx0 = (const int*)d_in[6];
    const int*   idx1 = (const int*)d_in[7];
    const float* Ws   = (const float*)d_in[8];
    const float* bsp  = (const float*)d_in[9];
    float* out = (float*)d_out;

    cudaFuncSetAttribute(k_gemm, cudaFuncAttributeMaxDynamicSharedMemorySize, SMEM_BYTES);

    k_prep_h<<<1750, 256>>>(h0, h1, h2, Ws);
    k_scatter_inv<<<16, 256>>>(idx0, idx1);
    k_convert_adj<<<82032, 256>>>(adj0, adj1, adj2);

    GemmCfg c1;
    c1.stage = 1;
    c1.seg[0] = {NL0, 128, 0,   0,        0,     0};
    c1.seg[1] = {NL1, 128, 125, 1024000,  49152, 3072000};
    c1.seg[2] = {NL2, 128, 188, 1536000,  98304, 4608000};
    k_gemm<<<220, 256, SMEM_BYTES>>>(c1);

    k_gather_y<<<2625, 256>>>(idx0, idx1);

    GemmCfg c2;
    c2.stage = 2;
    c2.seg[0] = {NL0, NL0, 0,   0,        0,       0};
    c2.seg[1] = {NL1, NL1, 125, 64000000, 3072000, 3072000};
    c2.seg[2] = {NL2, NL2, 188, 80000000, 4608000, 4608000};
    k_gemm<<<220, 256, SMEM_BYTES>>>(c2);

    k_epilogue<<<7000, 256>>>(bsp, out);
}